// round 10
// baseline (speedup 1.0000x reference)
#include <cuda_runtime.h>
#include <cuda_bf16.h>
#include <cstdint>

// out[128,1024] = x[128,1024] @ (w_pos - w_neg)[1024,1024] + (b_pos - b_neg)
// Memristor scaling cancels exactly (G_OFF in the differential pair, k_cond &
// K_V in the rescale; max_w never needed).
// 3-term bf16 hi/lo emulation on HMMA (baseline PTX mma.sync):
//   x = xh+xl, d = dh+dl;  out ~= xh@dh + xh@dl + xl@dh   (xl@dl ~2^-16)
//
// Round 10: 16 warps/SM (512-thr CTAs) + pipelined cp.async ring. CTA tile
// 64M x 64N x 256K, 4 stages of k=64, 3-deep buffer ring. Grid 16x2x4 = 128
// CTAs. Occupancy is the empirically-proven lever (r4 vs r7/r9).

#define BATCH 128
#define NIN   1024
#define NOUT  1024
#define MT    64
#define TILE_N 64
#define KSPLIT 4
#define KPER  256
#define KC    64
#define NSTAGE 4          // KPER / KC
#define NBUF  3
#define RS    144         // smem row stride bytes (128B data + 16 pad)
#define A_STG (64 * RS)                       // 9216 per h/l
#define B_STG (64 * RS)                       // 9216 per h/l
#define STAGE_BYTES (2 * A_STG + 2 * B_STG)   // 36864

__device__ __nv_bfloat16 g_dh[NIN * NOUT];
__device__ __nv_bfloat16 g_dl[NIN * NOUT];
__device__ __nv_bfloat16 g_xh[BATCH * NIN];
__device__ __nv_bfloat16 g_xl[BATCH * NIN];

__device__ __forceinline__ uint32_t smem_u32(const void* p) {
    uint32_t a;
    asm("{ .reg .u64 t; cvta.to.shared.u64 t, %1; cvt.u32.u64 %0, t; }" : "=r"(a) : "l"(p));
    return a;
}
__device__ __forceinline__ void split_hl(float v, uint16_t& h, uint16_t& l) {
    __nv_bfloat16 bh = __float2bfloat16(v);
    h = __bfloat16_as_ushort(bh);
    float r = v - __bfloat162float(bh);
    l = __bfloat16_as_ushort(__float2bfloat16(r));
}
__device__ __forceinline__ void ldsm4(uint32_t* r, uint32_t a) {
    asm volatile("ldmatrix.sync.aligned.m8n8.x4.shared.b16 {%0,%1,%2,%3}, [%4];"
                 : "=r"(r[0]), "=r"(r[1]), "=r"(r[2]), "=r"(r[3]) : "r"(a));
}
__device__ __forceinline__ void ldsm4t(uint32_t* r, uint32_t a) {
    asm volatile("ldmatrix.sync.aligned.m8n8.x4.trans.shared.b16 {%0,%1,%2,%3}, [%4];"
                 : "=r"(r[0]), "=r"(r[1]), "=r"(r[2]), "=r"(r[3]) : "r"(a));
}
__device__ __forceinline__ void mma16816(float* d, const uint32_t* a,
                                         uint32_t b0, uint32_t b1) {
    asm volatile("mma.sync.aligned.m16n8k16.row.col.f32.bf16.bf16.f32 "
                 "{%0,%1,%2,%3}, {%4,%5,%6,%7}, {%8,%9}, {%0,%1,%2,%3};"
                 : "+f"(d[0]), "+f"(d[1]), "+f"(d[2]), "+f"(d[3])
                 : "r"(a[0]), "r"(a[1]), "r"(a[2]), "r"(a[3]), "r"(b0), "r"(b1));
}
__device__ __forceinline__ void red_add_v2(float* p, float a, float b) {
    asm volatile("red.global.add.v2.f32 [%0], {%1, %2};"
                 :: "l"(p), "f"(a), "f"(b) : "memory");
}
__device__ __forceinline__ void cp_async16(uint32_t dst, const void* src) {
    asm volatile("cp.async.cg.shared.global [%0], [%1], 16;"
                 :: "r"(dst), "l"(src) : "memory");
}
__device__ __forceinline__ uint64_t pack4(uint16_t a, uint16_t b, uint16_t c, uint16_t d) {
    return (uint64_t)a | ((uint64_t)b << 16) | ((uint64_t)c << 32) | ((uint64_t)d << 48);
}

// ---- prep: split W diff and x into bf16 hi/lo; write bias diff into out ----
extern "C" __global__ void __launch_bounds__(256)
memr_prep(const float* __restrict__ x,
          const float* __restrict__ wp,
          const float* __restrict__ wn,
          const float* __restrict__ bp,
          const float* __restrict__ bn,
          float* __restrict__ out) {
    const int bid = blockIdx.x;
    const int t   = threadIdx.x;
    if (bid < 1024) {
        size_t base = ((size_t)bid * 256 + t) * 4;
        float4 p = *reinterpret_cast<const float4*>(wp + base);
        float4 n = *reinterpret_cast<const float4*>(wn + base);
        uint16_t h0, h1, h2, h3, l0, l1, l2, l3;
        split_hl(p.x - n.x, h0, l0); split_hl(p.y - n.y, h1, l1);
        split_hl(p.z - n.z, h2, l2); split_hl(p.w - n.w, h3, l3);
        *reinterpret_cast<uint64_t*>(g_dh + base) = pack4(h0, h1, h2, h3);
        *reinterpret_cast<uint64_t*>(g_dl + base) = pack4(l0, l1, l2, l3);
    } else if (bid < 1152) {
        size_t base = ((size_t)(bid - 1024) * 256 + t) * 4;
        float4 v = *reinterpret_cast<const float4*>(x + base);
        uint16_t h0, h1, h2, h3, l0, l1, l2, l3;
        split_hl(v.x, h0, l0); split_hl(v.y, h1, l1);
        split_hl(v.z, h2, l2); split_hl(v.w, h3, l3);
        *reinterpret_cast<uint64_t*>(g_xh + base) = pack4(h0, h1, h2, h3);
        *reinterpret_cast<uint64_t*>(g_xl + base) = pack4(l0, l1, l2, l3);
    } else {
        size_t base = ((size_t)(bid - 1152) * 256 + t) * 4;
        int o = (int)(base & (NOUT - 1));
        float4 vp = *reinterpret_cast<const float4*>(bp + o);
        float4 vn = *reinterpret_cast<const float4*>(bn + o);
        *reinterpret_cast<float4*>(out + base) =
            make_float4(vp.x - vn.x, vp.y - vn.y, vp.z - vn.z, vp.w - vn.w);
    }
}

// ---- pipelined GEMM: 512 threads, 16 warps = 4M x 4N ----
extern "C" __global__ void __launch_bounds__(512, 1)
memr_gemm_hmma(float* __restrict__ out) {
    extern __shared__ char smem_raw[];
    const uint32_t base = smem_u32(smem_raw);

    const int t    = threadIdx.x;
    const int wid  = t >> 5;
    const int lane = t & 31;
    const int j0 = blockIdx.x * TILE_N;
    const int m0 = blockIdx.y * MT;
    const int k0 = blockIdx.z * KPER;

    auto issue_stage = [&](int s, int buf) {
        const uint32_t sb = base + (uint32_t)buf * STAGE_BYTES;
        const int kb = k0 + s * KC;
        // A: 1024 x 16B chunks (xh then xl); 2 per thread
#pragma unroll
        for (int i = 0; i < 2; i++) {
            int id  = t + 512 * i;
            int hl  = id >> 9;
            int c   = id & 511;
            int row = c >> 3;          // 64 rows, 8 chunks each
            int ch  = c & 7;
            uint32_t dst = sb + (uint32_t)hl * A_STG + (uint32_t)row * RS + (uint32_t)ch * 16;
            const __nv_bfloat16* src =
                (hl ? g_xl : g_xh) + (size_t)(m0 + row) * NIN + kb + ch * 8;
            cp_async16(dst, src);
        }
        // B: 1024 x 16B chunks (dh then dl); 2 per thread
#pragma unroll
        for (int i = 0; i < 2; i++) {
            int id  = t + 512 * i;
            int hl  = id >> 9;
            int c   = id & 511;
            int row = c >> 3;          // 64 k-rows, 8 chunks each
            int ch  = c & 7;
            uint32_t dst = sb + 2 * A_STG + (uint32_t)hl * B_STG +
                           (uint32_t)row * RS + (uint32_t)ch * 16;
            const __nv_bfloat16* src =
                (hl ? g_dl : g_dh) + (size_t)(kb + row) * NOUT + j0 + ch * 8;
            cp_async16(dst, src);
        }
        asm volatile("cp.async.commit_group;" ::: "memory");
    };

    // warp tiling: 16 warps = 4(M,16) x 4(N,16)
    const int wm  = wid >> 2;
    const int wn2 = wid & 3;
    const uint32_t aOff = (uint32_t)(wm * 16 + (lane & 15)) * RS + (uint32_t)((lane >> 4) * 16);
    const uint32_t bOff = (uint32_t)(lane & 15) * RS + (uint32_t)(wn2 * 16 + (lane >> 4) * 8) * 2;

    float acc[2][4];
#pragma unroll
    for (int n = 0; n < 2; n++)
#pragma unroll
        for (int i = 0; i < 4; i++) acc[n][i] = 0.0f;

    issue_stage(0, 0);
    issue_stage(1, 1);
    issue_stage(2, 2);

#pragma unroll
    for (int s = 0; s < NSTAGE; s++) {
        // guarantee group s retired (issued: 3 for s=0, then 4)
        if (s < 2)       asm volatile("cp.async.wait_group 2;" ::: "memory");
        else if (s == 2) asm volatile("cp.async.wait_group 1;" ::: "memory");
        else             asm volatile("cp.async.wait_group 0;" ::: "memory");
        __syncthreads();

        const uint32_t sb = base + (uint32_t)(s % NBUF) * STAGE_BYTES;
        const uint32_t aH = sb + aOff;
        const uint32_t aL = sb + A_STG + aOff;
        const uint32_t bH = sb + 2 * A_STG + bOff;
        const uint32_t bL = sb + 2 * A_STG + B_STG + bOff;

#pragma unroll
        for (int q = 0; q < 4; q++) {           // 4 k16-steps per stage
            const uint32_t soA = (uint32_t)q * 32;
            const uint32_t soB = (uint32_t)(q * 16) * RS;
            uint32_t ah[4], al[4], bh[4], bl[4];
            ldsm4 (ah, aH + soA);
            ldsm4 (al, aL + soA);
            ldsm4t(bh, bH + soB);
            ldsm4t(bl, bL + soB);
            // interleave accumulators to shorten dependent HMMA chains
            mma16816(acc[0], ah, bh[0], bh[1]);
            mma16816(acc[1], ah, bh[2], bh[3]);
            mma16816(acc[0], ah, bl[0], bl[1]);
            mma16816(acc[1], ah, bl[2], bl[3]);
            mma16816(acc[0], al, bh[0], bh[1]);
            mma16816(acc[1], al, bh[2], bh[3]);
        }
        __syncthreads();

        if (s + 3 < NSTAGE) issue_stage(s + 3, (s + 3) % NBUF);
    }

    // ---- epilogue: red.v2 into out (KSPLIT=4 writers per address) ----
    const int r0 = m0 + wm * 16 + (lane >> 2);
    const int c0 = j0 + wn2 * 16 + 2 * (lane & 3);
#pragma unroll
    for (int n = 0; n < 2; n++) {
        red_add_v2(out + (size_t)r0 * NOUT + c0 + n * 8, acc[n][0], acc[n][1]);
        red_add_v2(out + (size_t)(r0 + 8) * NOUT + c0 + n * 8, acc[n][2], acc[n][3]);
    }
}

extern "C" void kernel_launch(void* const* d_in, const int* in_sizes, int n_in,
                              void* d_out, int out_size) {
    const float* x  = (const float*)d_in[0];
    const float* wp = (const float*)d_in[1];
    const float* wn = (const float*)d_in[2];
    const float* bp = (const float*)d_in[3];
    const float* bn = (const float*)d_in[4];
    float* out = (float*)d_out;

    const int smem_bytes = NBUF * STAGE_BYTES;   // 110592
    cudaFuncSetAttribute(memr_gemm_hmma,
                         cudaFuncAttributeMaxDynamicSharedMemorySize, smem_bytes);

    memr_prep<<<1280, 256>>>(x, wp, wn, bp, bn, out);
    dim3 grid(NOUT / TILE_N, BATCH / MT, KSPLIT);   // 16 x 2 x 4
    memr_gemm_hmma<<<grid, 512, smem_bytes>>>(out);
}

// round 11
// speedup vs baseline: 1.0357x; 1.0357x over previous
#include <cuda_runtime.h>
#include <cuda_bf16.h>
#include <cstdint>

// out[128,1024] = x[128,1024] @ (w_pos - w_neg)[1024,1024] + (b_pos - b_neg)
// Memristor scaling cancels exactly (G_OFF in the differential pair, k_cond &
// K_V in the rescale; max_w never needed).
// 3-term bf16 hi/lo emulation on HMMA (baseline PTX mma.sync):
//   x = xh+xl, d = dh+dl;  out ~= xh@dh + xh@dl + xl@dh   (xl@dl ~2^-16)
//
// Round 11: the empirically-fastest GEMM (round-4 monolithic kernel: whole
// tile loaded in one LDG burst, in-kernel convert, one sync, barrier-free
// compute) + the empirically-cheap epilogue (round-5 init + red.global.add.v2)
// replacing the 3-5us split-K reduce kernel. Single-variable change.

#define BATCH 128
#define NIN   1024
#define NOUT  1024
#define KSPLIT 8
#define KCHUNK 128      // NIN / KSPLIT
#define TILE_N 64
#define NT 16           // NOUT / TILE_N
#define RA 272          // A smem row stride bytes (128 bf16 = 256B + 16 pad)
#define RB 144          // B smem row stride bytes (64 bf16 = 128B + 16 pad)

__device__ __forceinline__ uint32_t smem_u32(const void* p) {
    uint32_t a;
    asm("{ .reg .u64 t; cvta.to.shared.u64 t, %1; cvt.u32.u64 %0, t; }" : "=r"(a) : "l"(p));
    return a;
}

__device__ __forceinline__ void split_hl(float v, uint16_t& h, uint16_t& l) {
    __nv_bfloat16 bh = __float2bfloat16(v);
    h = __bfloat16_as_ushort(bh);
    float r = v - __bfloat162float(bh);
    l = __bfloat16_as_ushort(__float2bfloat16(r));
}

__device__ __forceinline__ void ldsm4(uint32_t* r, uint32_t a) {
    asm volatile("ldmatrix.sync.aligned.m8n8.x4.shared.b16 {%0,%1,%2,%3}, [%4];"
                 : "=r"(r[0]), "=r"(r[1]), "=r"(r[2]), "=r"(r[3]) : "r"(a));
}
__device__ __forceinline__ void ldsm4t(uint32_t* r, uint32_t a) {
    asm volatile("ldmatrix.sync.aligned.m8n8.x4.trans.shared.b16 {%0,%1,%2,%3}, [%4];"
                 : "=r"(r[0]), "=r"(r[1]), "=r"(r[2]), "=r"(r[3]) : "r"(a));
}
__device__ __forceinline__ void mma16816(float* d, const uint32_t* a,
                                         uint32_t b0, uint32_t b1) {
    asm volatile("mma.sync.aligned.m16n8k16.row.col.f32.bf16.bf16.f32 "
                 "{%0,%1,%2,%3}, {%4,%5,%6,%7}, {%8,%9}, {%0,%1,%2,%3};"
                 : "+f"(d[0]), "+f"(d[1]), "+f"(d[2]), "+f"(d[3])
                 : "r"(a[0]), "r"(a[1]), "r"(a[2]), "r"(a[3]), "r"(b0), "r"(b1));
}
__device__ __forceinline__ void red_add_v2(float* p, float a, float b) {
    asm volatile("red.global.add.v2.f32 [%0], {%1, %2};"
                 :: "l"(p), "f"(a), "f"(b) : "memory");
}

// ---- init: out = b_pos - b_neg broadcast over batch rows ----
extern "C" __global__ void __launch_bounds__(256)
memr_init_kernel(const float* __restrict__ bp,
                 const float* __restrict__ bn,
                 float* __restrict__ out) {
    int id   = blockIdx.x * 256 + threadIdx.x;   // 0..32767
    int base = id * 4;
    int o    = base & (NOUT - 1);
    float4 vp = *reinterpret_cast<const float4*>(bp + o);
    float4 vn = *reinterpret_cast<const float4*>(bn + o);
    *reinterpret_cast<float4*>(out + base) =
        make_float4(vp.x - vn.x, vp.y - vn.y, vp.z - vn.z, vp.w - vn.w);
}

extern "C" __global__ void __launch_bounds__(256, 1)
memr_gemm_hmma(const float* __restrict__ x,
               const float* __restrict__ wp,
               const float* __restrict__ wn,
               float* __restrict__ out) {
    extern __shared__ char smem_raw[];
    const uint32_t Ah = smem_u32(smem_raw);       // xh [128 b][128 k] bf16
    const uint32_t Al = Ah + 128 * RA;            // xl
    const uint32_t Bh = Al + 128 * RA;            // dh [128 k][64 o] bf16
    const uint32_t Bl = Bh + 128 * RB;            // dl

    const int t  = threadIdx.x;
    const int jt = blockIdx.x;        // N tile (64 cols)
    const int ks = blockIdx.y;        // K split (128 k)
    const int k0 = ks * KCHUNK;
    const int j0 = jt * TILE_N;

    // ---- x tile: [128 b, k0:k0+128], coalesced float4, hi/lo split ----
#pragma unroll 4
    for (int i = 0; i < 16; i++) {
        int id  = t + 256 * i;
        int row = id >> 5;            // batch row (32 float4 per row)
        int kq  = id & 31;
        float4 v = *reinterpret_cast<const float4*>(x + (size_t)row * NIN + k0 + kq * 4);
        uint16_t h0, h1, h2, h3, l0, l1, l2, l3;
        split_hl(v.x, h0, l0); split_hl(v.y, h1, l1);
        split_hl(v.z, h2, l2); split_hl(v.w, h3, l3);
        uint64_t hv = (uint64_t)((uint32_t)h0 | ((uint32_t)h1 << 16)) |
                      ((uint64_t)((uint32_t)h2 | ((uint32_t)h3 << 16)) << 32);
        uint64_t lv = (uint64_t)((uint32_t)l0 | ((uint32_t)l1 << 16)) |
                      ((uint64_t)((uint32_t)l2 | ((uint32_t)l3 << 16)) << 32);
        uint32_t off = (uint32_t)row * RA + (uint32_t)kq * 8;
        asm volatile("st.shared.b64 [%0], %1;" :: "r"(Ah + off), "l"(hv) : "memory");
        asm volatile("st.shared.b64 [%0], %1;" :: "r"(Al + off), "l"(lv) : "memory");
    }

    // ---- W tile: row-major coalesced float4, diff+split, store [k][o] ----
#pragma unroll 4
    for (int i = 0; i < 8; i++) {
        int id = t + 256 * i;
        int k  = id >> 4;             // k row (16 float4 per row of 64 floats)
        int oq = id & 15;
        const float4 p = *reinterpret_cast<const float4*>(wp + (size_t)(k0 + k) * NOUT + j0 + oq * 4);
        const float4 n = *reinterpret_cast<const float4*>(wn + (size_t)(k0 + k) * NOUT + j0 + oq * 4);
        uint16_t h0, h1, h2, h3, l0, l1, l2, l3;
        split_hl(p.x - n.x, h0, l0); split_hl(p.y - n.y, h1, l1);
        split_hl(p.z - n.z, h2, l2); split_hl(p.w - n.w, h3, l3);
        uint64_t hv = (uint64_t)((uint32_t)h0 | ((uint32_t)h1 << 16)) |
                      ((uint64_t)((uint32_t)h2 | ((uint32_t)h3 << 16)) << 32);
        uint64_t lv = (uint64_t)((uint32_t)l0 | ((uint32_t)l1 << 16)) |
                      ((uint64_t)((uint32_t)l2 | ((uint32_t)l3 << 16)) << 32);
        uint32_t off = (uint32_t)k * RB + (uint32_t)oq * 8;
        asm volatile("st.shared.b64 [%0], %1;" :: "r"(Bh + off), "l"(hv) : "memory");
        asm volatile("st.shared.b64 [%0], %1;" :: "r"(Bl + off), "l"(lv) : "memory");
    }
    __syncthreads();

    // ---- compute: 8 warps as 4(M) x 2(N); warp tile 32 rows x 32 cols ----
    const int wid  = t >> 5;
    const int lane = t & 31;
    const int wm  = wid >> 1;         // rows 32*wm
    const int wn2 = wid & 1;          // cols 32*wn2

    float acc[2][4][4];
#pragma unroll
    for (int mt = 0; mt < 2; mt++)
#pragma unroll
        for (int n = 0; n < 4; n++)
#pragma unroll
            for (int i = 0; i < 4; i++) acc[mt][n][i] = 0.0f;

    // A (row-major) lane addr: row = wm*32 + (lane&15), 16B col chunk = lane>>4
    const uint32_t aOff = (uint32_t)(wm * 32 + (lane & 15)) * RA + (uint32_t)((lane >> 4) * 16);
    // B (x4.trans from [k][o]) lane addr: k row = lane&15, col = wn2*32 + (lane>>4)*8
    const uint32_t bOff = (uint32_t)(lane & 15) * RB + (uint32_t)(wn2 * 32 + (lane >> 4) * 8) * 2;
    const uint32_t aH = Ah + aOff, aL = Al + aOff;
    const uint32_t bH = Bh + bOff, bL = Bl + bOff;

#pragma unroll
    for (int s = 0; s < 8; s++) {
        const uint32_t soA = (uint32_t)s * 32;        // 16 bf16 along k
        const uint32_t soB = (uint32_t)(s * 16) * RB; // 16 k-rows down
        uint32_t ah[2][4], al[2][4];
        ldsm4(ah[0], aH + soA);
        ldsm4(ah[1], aH + 16 * RA + soA);
        ldsm4(al[0], aL + soA);
        ldsm4(al[1], aL + 16 * RA + soA);
        uint32_t bhr[2][4], blr[2][4];
        ldsm4t(bhr[0], bH + soB);
        ldsm4t(bhr[1], bH + soB + 32);    // cols +16
        ldsm4t(blr[0], bL + soB);
        ldsm4t(blr[1], bL + soB + 32);
#pragma unroll
        for (int n = 0; n < 4; n++) {
            const int g = n >> 1, j = n & 1;
            const uint32_t b0h = bhr[g][2 * j], b1h = bhr[g][2 * j + 1];
            const uint32_t b0l = blr[g][2 * j], b1l = blr[g][2 * j + 1];
#pragma unroll
            for (int mt = 0; mt < 2; mt++) {
                mma16816(acc[mt][n], ah[mt], b0h, b1h);
                mma16816(acc[mt][n], ah[mt], b0l, b1l);
                mma16816(acc[mt][n], al[mt], b0h, b1h);
            }
        }
    }

    // ---- epilogue: accumulate warp block 32x32 into out via red.v2 ----
    const int r0 = wm * 32 + (lane >> 2);
    const int c0 = j0 + wn2 * 32 + 2 * (lane & 3);
#pragma unroll
    for (int mt = 0; mt < 2; mt++) {
#pragma unroll
        for (int n = 0; n < 4; n++) {
            int row = r0 + mt * 16;
            int col = c0 + n * 8;
            red_add_v2(out + (size_t)row * NOUT + col, acc[mt][n][0], acc[mt][n][1]);
            red_add_v2(out + (size_t)(row + 8) * NOUT + col, acc[mt][n][2], acc[mt][n][3]);
        }
    }
}

extern "C" void kernel_launch(void* const* d_in, const int* in_sizes, int n_in,
                              void* d_out, int out_size) {
    const float* x  = (const float*)d_in[0];
    const float* wp = (const float*)d_in[1];
    const float* wn = (const float*)d_in[2];
    const float* bp = (const float*)d_in[3];
    const float* bn = (const float*)d_in[4];
    float* out = (float*)d_out;

    const int smem_bytes = 2 * 128 * RA + 2 * 128 * RB;   // 106496
    cudaFuncSetAttribute(memr_gemm_hmma,
                         cudaFuncAttributeMaxDynamicSharedMemorySize, smem_bytes);

    memr_init_kernel<<<128, 256>>>(bp, bn, out);
    dim3 grid(NT, KSPLIT);
    memr_gemm_hmma<<<grid, 256, smem_bytes>>>(x, wp, wn, out);
}

// round 14
// speedup vs baseline: 1.1976x; 1.1563x over previous
#include <cuda_runtime.h>
#include <cuda_fp16.h>
#include <cstdint>

// out[128,1024] = x[128,1024] @ (w_pos - w_neg)[1024,1024] + (b_pos - b_neg)
// Memristor scaling cancels exactly (G_OFF in the differential pair, k_cond &
// K_V in the rescale; max_w never needed).
//
// Round 14 (= round-12 design, PTX typo fixed): single-pass fp16 HMMA.
// All prior GEMM variants were bound by mma.sync issue count (~30cyc/SMSP/op
// legacy path on sm_103); fp16 single-term cuts the MMA count 3x vs the bf16
// hi/lo scheme. fp16 rounding -> norm rel_err ~4e-4 < 1e-3 (fp32 accumulate).

#define BATCH 128
#define NIN   1024
#define NOUT  1024
#define KSPLIT 16
#define KCHUNK 64       // NIN / KSPLIT
#define TILE_N 64
#define NT 16           // NOUT / TILE_N
#define RA 144          // A smem row stride bytes (64 fp16 = 128B + 16 pad)
#define RB 144          // B smem row stride bytes (64 fp16 = 128B + 16 pad)

__device__ __forceinline__ uint32_t smem_u32(const void* p) {
    uint32_t a;
    asm("{ .reg .u64 t; cvta.to.shared.u64 t, %1; cvt.u32.u64 %0, t; }" : "=r"(a) : "l"(p));
    return a;
}
__device__ __forceinline__ void ldsm4(uint32_t* r, uint32_t a) {
    asm volatile("ldmatrix.sync.aligned.m8n8.x4.shared.b16 {%0,%1,%2,%3}, [%4];"
                 : "=r"(r[0]), "=r"(r[1]), "=r"(r[2]), "=r"(r[3]) : "r"(a));
}
__device__ __forceinline__ void ldsm4t(uint32_t* r, uint32_t a) {
    asm volatile("ldmatrix.sync.aligned.m8n8.x4.trans.shared.b16 {%0,%1,%2,%3}, [%4];"
                 : "=r"(r[0]), "=r"(r[1]), "=r"(r[2]), "=r"(r[3]) : "r"(a));
}
__device__ __forceinline__ void mma16816h(float* d, const uint32_t* a,
                                          uint32_t b0, uint32_t b1) {
    asm volatile("mma.sync.aligned.m16n8k16.row.col.f32.f16.f16.f32 "
                 "{%0,%1,%2,%3}, {%4,%5,%6,%7}, {%8,%9}, {%0,%1,%2,%3};"
                 : "+f"(d[0]), "+f"(d[1]), "+f"(d[2]), "+f"(d[3])
                 : "r"(a[0]), "r"(a[1]), "r"(a[2]), "r"(a[3]), "r"(b0), "r"(b1));
}
__device__ __forceinline__ void red_add_v2(float* p, float a, float b) {
    asm volatile("red.global.add.v2.f32 [%0], {%1, %2};"
                 :: "l"(p), "f"(a), "f"(b) : "memory");
}
__device__ __forceinline__ uint64_t pack4h(float a, float b, float c, float d) {
    uint16_t h0 = __half_as_ushort(__float2half_rn(a));
    uint16_t h1 = __half_as_ushort(__float2half_rn(b));
    uint16_t h2 = __half_as_ushort(__float2half_rn(c));
    uint16_t h3 = __half_as_ushort(__float2half_rn(d));
    return (uint64_t)h0 | ((uint64_t)h1 << 16) | ((uint64_t)h2 << 32) | ((uint64_t)h3 << 48);
}

// ---- init: out = b_pos - b_neg broadcast over batch rows ----
extern "C" __global__ void __launch_bounds__(256)
memr_init_kernel(const float* __restrict__ bp,
                 const float* __restrict__ bn,
                 float* __restrict__ out) {
    int id   = blockIdx.x * 256 + threadIdx.x;   // 0..32767
    int base = id * 4;
    int o    = base & (NOUT - 1);
    float4 vp = *reinterpret_cast<const float4*>(bp + o);
    float4 vn = *reinterpret_cast<const float4*>(bn + o);
    *reinterpret_cast<float4*>(out + base) =
        make_float4(vp.x - vn.x, vp.y - vn.y, vp.z - vn.z, vp.w - vn.w);
}

extern "C" __global__ void __launch_bounds__(256, 2)
memr_gemm_hmma(const float* __restrict__ x,
               const float* __restrict__ wp,
               const float* __restrict__ wn,
               float* __restrict__ out) {
    extern __shared__ char smem_raw[];
    const uint32_t A = smem_u32(smem_raw);        // x  [128 b][64 k] fp16
    const uint32_t B = A + 128 * RA;              // d  [64 k][64 o] fp16

    const int t  = threadIdx.x;
    const int jt = blockIdx.x;        // N tile (64 cols)
    const int ks = blockIdx.y;        // K split (64 k)
    const int k0 = ks * KCHUNK;
    const int j0 = jt * TILE_N;

    // ---- x tile: [128 b, k0:k0+64], coalesced float4 -> fp16 ----
#pragma unroll 4
    for (int i = 0; i < 8; i++) {
        int id  = t + 256 * i;
        int row = id >> 4;            // batch row (16 float4 per row)
        int kq  = id & 15;
        float4 v = *reinterpret_cast<const float4*>(x + (size_t)row * NIN + k0 + kq * 4);
        uint64_t hv = pack4h(v.x, v.y, v.z, v.w);
        uint32_t off = (uint32_t)row * RA + (uint32_t)kq * 8;
        asm volatile("st.shared.b64 [%0], %1;" :: "r"(A + off), "l"(hv) : "memory");
    }

    // ---- W tile: [64 k, 64 o] row-major coalesced, diff -> fp16 ----
#pragma unroll 4
    for (int i = 0; i < 4; i++) {
        int id = t + 256 * i;
        int k  = id >> 4;             // k row (16 float4 per row)
        int oq = id & 15;
        const float4 p = *reinterpret_cast<const float4*>(wp + (size_t)(k0 + k) * NOUT + j0 + oq * 4);
        const float4 n = *reinterpret_cast<const float4*>(wn + (size_t)(k0 + k) * NOUT + j0 + oq * 4);
        uint64_t hv = pack4h(p.x - n.x, p.y - n.y, p.z - n.z, p.w - n.w);
        uint32_t off = (uint32_t)k * RB + (uint32_t)oq * 8;
        asm volatile("st.shared.b64 [%0], %1;" :: "r"(B + off), "l"(hv) : "memory");
    }
    __syncthreads();

    // ---- compute: 8 warps as 4(M) x 2(N); warp tile 32 rows x 32 cols ----
    const int wid  = t >> 5;
    const int lane = t & 31;
    const int wm  = wid >> 1;         // rows 32*wm
    const int wn2 = wid & 1;          // cols 32*wn2

    float acc[2][4][4];
#pragma unroll
    for (int mt = 0; mt < 2; mt++)
#pragma unroll
        for (int n = 0; n < 4; n++)
#pragma unroll
            for (int i = 0; i < 4; i++) acc[mt][n][i] = 0.0f;

    const uint32_t aOff = (uint32_t)(wm * 32 + (lane & 15)) * RA + (uint32_t)((lane >> 4) * 16);
    const uint32_t bOff = (uint32_t)(lane & 15) * RB + (uint32_t)(wn2 * 32 + (lane >> 4) * 8) * 2;
    const uint32_t aP = A + aOff;
    const uint32_t bP = B + bOff;

#pragma unroll
    for (int s = 0; s < 4; s++) {                 // 4 k16-steps
        const uint32_t soA = (uint32_t)s * 32;    // 16 fp16 = 32B along k
        const uint32_t soB = (uint32_t)(s * 16) * RB;
        uint32_t a0[4], a1[4];
        ldsm4(a0, aP + soA);
        ldsm4(a1, aP + 16 * RA + soA);
        uint32_t br[2][4];
        ldsm4t(br[0], bP + soB);
        ldsm4t(br[1], bP + soB + 32);             // cols +16
#pragma unroll
        for (int n = 0; n < 4; n++) {
            const int g = n >> 1, j = n & 1;
            const uint32_t b0 = br[g][2 * j], b1 = br[g][2 * j + 1];
            mma16816h(acc[0][n], a0, b0, b1);
            mma16816h(acc[1][n], a1, b0, b1);
        }
    }

    // ---- epilogue: accumulate warp block 32x32 into out via red.v2 ----
    const int r0 = wm * 32 + (lane >> 2);
    const int c0 = j0 + wn2 * 32 + 2 * (lane & 3);
#pragma unroll
    for (int mt = 0; mt < 2; mt++) {
#pragma unroll
        for (int n = 0; n < 4; n++) {
            int row = r0 + mt * 16;
            int col = c0 + n * 8;
            red_add_v2(out + (size_t)row * NOUT + col, acc[mt][n][0], acc[mt][n][1]);
            red_add_v2(out + (size_t)(row + 8) * NOUT + col, acc[mt][n][2], acc[mt][n][3]);
        }
    }
}

extern "C" void kernel_launch(void* const* d_in, const int* in_sizes, int n_in,
                              void* d_out, int out_size) {
    const float* x  = (const float*)d_in[0];
    const float* wp = (const float*)d_in[1];
    const float* wn = (const float*)d_in[2];
    const float* bp = (const float*)d_in[3];
    const float* bn = (const float*)d_in[4];
    float* out = (float*)d_out;

    const int smem_bytes = 128 * RA + 64 * RB;   // 27648 (< 48KB default)

    memr_init_kernel<<<128, 256>>>(bp, bn, out);
    dim3 grid(NT, KSPLIT);                        // 16 x 16 = 256 CTAs
    memr_gemm_hmma<<<grid, 256, smem_bytes>>>(x, wp, wn, out);
}

// round 15
// speedup vs baseline: 1.2119x; 1.0119x over previous
#include <cuda_runtime.h>
#include <cuda_fp16.h>
#include <cstdint>

// out[128,1024] = x[128,1024] @ (w_pos - w_neg)[1024,1024] + (b_pos - b_neg)
// Memristor scaling cancels exactly; fp16 single-pass HMMA (fp32 accumulate),
// rel_err ~3e-4 (validated r14).
//
// Round 15: cut REDG epilogue volume 4x (KSPLIT 16->4). REDG costs ~41cyc of
// LSU occupancy per red.v2 warp-op (1.29cyc/lane); r14's 1M v2-ops = ~2.4us
// chip-wide LSU serialization. Grid held at 128 CTAs by splitting M (2 tiles).

#define BATCH 128
#define NIN   1024
#define NOUT  1024
#define MT    64        // M per CTA
#define TILE_N 64
#define NT 16           // NOUT / TILE_N
#define KSPLIT 4
#define KCHUNK 256      // NIN / KSPLIT
#define RA 528          // A smem row stride bytes (256 fp16 = 512B + 16 pad)
#define RB 144          // B smem row stride bytes (64 fp16 = 128B + 16 pad)

__device__ __forceinline__ uint32_t smem_u32(const void* p) {
    uint32_t a;
    asm("{ .reg .u64 t; cvta.to.shared.u64 t, %1; cvt.u32.u64 %0, t; }" : "=r"(a) : "l"(p));
    return a;
}
__device__ __forceinline__ void ldsm4(uint32_t* r, uint32_t a) {
    asm volatile("ldmatrix.sync.aligned.m8n8.x4.shared.b16 {%0,%1,%2,%3}, [%4];"
                 : "=r"(r[0]), "=r"(r[1]), "=r"(r[2]), "=r"(r[3]) : "r"(a));
}
__device__ __forceinline__ void ldsm4t(uint32_t* r, uint32_t a) {
    asm volatile("ldmatrix.sync.aligned.m8n8.x4.trans.shared.b16 {%0,%1,%2,%3}, [%4];"
                 : "=r"(r[0]), "=r"(r[1]), "=r"(r[2]), "=r"(r[3]) : "r"(a));
}
__device__ __forceinline__ void mma16816h(float* d, const uint32_t* a,
                                          uint32_t b0, uint32_t b1) {
    asm volatile("mma.sync.aligned.m16n8k16.row.col.f32.f16.f16.f32 "
                 "{%0,%1,%2,%3}, {%4,%5,%6,%7}, {%8,%9}, {%0,%1,%2,%3};"
                 : "+f"(d[0]), "+f"(d[1]), "+f"(d[2]), "+f"(d[3])
                 : "r"(a[0]), "r"(a[1]), "r"(a[2]), "r"(a[3]), "r"(b0), "r"(b1));
}
__device__ __forceinline__ void red_add_v2(float* p, float a, float b) {
    asm volatile("red.global.add.v2.f32 [%0], {%1, %2};"
                 :: "l"(p), "f"(a), "f"(b) : "memory");
}
__device__ __forceinline__ uint64_t pack4h(float a, float b, float c, float d) {
    uint16_t h0 = __half_as_ushort(__float2half_rn(a));
    uint16_t h1 = __half_as_ushort(__float2half_rn(b));
    uint16_t h2 = __half_as_ushort(__float2half_rn(c));
    uint16_t h3 = __half_as_ushort(__float2half_rn(d));
    return (uint64_t)h0 | ((uint64_t)h1 << 16) | ((uint64_t)h2 << 32) | ((uint64_t)h3 << 48);
}

// ---- init: out = b_pos - b_neg broadcast over batch rows ----
extern "C" __global__ void __launch_bounds__(256)
memr_init_kernel(const float* __restrict__ bp,
                 const float* __restrict__ bn,
                 float* __restrict__ out) {
    int id   = blockIdx.x * 256 + threadIdx.x;   // 0..32767
    int base = id * 4;
    int o    = base & (NOUT - 1);
    float4 vp = *reinterpret_cast<const float4*>(bp + o);
    float4 vn = *reinterpret_cast<const float4*>(bn + o);
    *reinterpret_cast<float4*>(out + base) =
        make_float4(vp.x - vn.x, vp.y - vn.y, vp.z - vn.z, vp.w - vn.w);
}

// ---- GEMM: grid (16 jt, 2 mt, 4 ks) = 128 CTAs; tile 64M x 64N x 256K ----
extern "C" __global__ void __launch_bounds__(256, 2)
memr_gemm_hmma(const float* __restrict__ x,
               const float* __restrict__ wp,
               const float* __restrict__ wn,
               float* __restrict__ out) {
    extern __shared__ char smem_raw[];
    const uint32_t A = smem_u32(smem_raw);        // x  [64 b][256 k] fp16
    const uint32_t B = A + MT * RA;               // d  [256 k][64 o] fp16

    const int t  = threadIdx.x;
    const int j0 = blockIdx.x * TILE_N;
    const int m0 = blockIdx.y * MT;
    const int k0 = blockIdx.z * KCHUNK;

    // ---- x tile: [64 b, k0:k0+256], coalesced float4 -> fp16 ----
#pragma unroll 4
    for (int i = 0; i < 16; i++) {
        int id  = t + 256 * i;
        int row = id >> 6;            // 64 float4 per row
        int kq  = id & 63;
        float4 v = *reinterpret_cast<const float4*>(x + (size_t)(m0 + row) * NIN + k0 + kq * 4);
        uint64_t hv = pack4h(v.x, v.y, v.z, v.w);
        uint32_t off = (uint32_t)row * RA + (uint32_t)kq * 8;
        asm volatile("st.shared.b64 [%0], %1;" :: "r"(A + off), "l"(hv) : "memory");
    }

    // ---- W tile: [256 k, 64 o] row-major coalesced, diff -> fp16 ----
#pragma unroll 4
    for (int i = 0; i < 16; i++) {
        int id = t + 256 * i;
        int k  = id >> 4;             // 16 float4 per row
        int oq = id & 15;
        const float4 p = *reinterpret_cast<const float4*>(wp + (size_t)(k0 + k) * NOUT + j0 + oq * 4);
        const float4 n = *reinterpret_cast<const float4*>(wn + (size_t)(k0 + k) * NOUT + j0 + oq * 4);
        uint64_t hv = pack4h(p.x - n.x, p.y - n.y, p.z - n.z, p.w - n.w);
        uint32_t off = (uint32_t)k * RB + (uint32_t)oq * 8;
        asm volatile("st.shared.b64 [%0], %1;" :: "r"(B + off), "l"(hv) : "memory");
    }
    __syncthreads();

    // ---- compute: 8 warps as 2(M:32) x 4(N:16); warp tile 32 x 16 ----
    const int wid  = t >> 5;
    const int lane = t & 31;
    const int wm  = wid >> 2;         // rows 32*wm
    const int wn2 = wid & 3;          // cols 16*wn2

    float acc[2][2][4];               // [mfrag16][nfrag8][4]
#pragma unroll
    for (int mt = 0; mt < 2; mt++)
#pragma unroll
        for (int n = 0; n < 2; n++)
#pragma unroll
            for (int i = 0; i < 4; i++) acc[mt][n][i] = 0.0f;

    const uint32_t aOff = (uint32_t)(wm * 32 + (lane & 15)) * RA + (uint32_t)((lane >> 4) * 16);
    const uint32_t bOff = (uint32_t)(lane & 15) * RB + (uint32_t)(wn2 * 16 + (lane >> 4) * 8) * 2;
    const uint32_t aP = A + aOff;
    const uint32_t bP = B + bOff;

#pragma unroll
    for (int s = 0; s < 16; s++) {                // 16 k16-steps
        const uint32_t soA = (uint32_t)s * 32;    // 16 fp16 = 32B along k
        const uint32_t soB = (uint32_t)(s * 16) * RB;
        uint32_t a0[4], a1[4], br[4];
        ldsm4(a0, aP + soA);
        ldsm4(a1, aP + 16 * RA + soA);
        ldsm4t(br, bP + soB);                     // 16 cols = 2 n8 frags
        mma16816h(acc[0][0], a0, br[0], br[1]);
        mma16816h(acc[1][0], a1, br[0], br[1]);
        mma16816h(acc[0][1], a0, br[2], br[3]);
        mma16816h(acc[1][1], a1, br[2], br[3]);
    }

    // ---- epilogue: warp block 32x16 -> out via red.v2 (4 writers/addr) ----
    const int r0 = m0 + wm * 32 + (lane >> 2);
    const int c0 = j0 + wn2 * 16 + 2 * (lane & 3);
#pragma unroll
    for (int mt = 0; mt < 2; mt++) {
#pragma unroll
        for (int n = 0; n < 2; n++) {
            int row = r0 + mt * 16;
            int col = c0 + n * 8;
            red_add_v2(out + (size_t)row * NOUT + col, acc[mt][n][0], acc[mt][n][1]);
            red_add_v2(out + (size_t)(row + 8) * NOUT + col, acc[mt][n][2], acc[mt][n][3]);
        }
    }
}

extern "C" void kernel_launch(void* const* d_in, const int* in_sizes, int n_in,
                              void* d_out, int out_size) {
    const float* x  = (const float*)d_in[0];
    const float* wp = (const float*)d_in[1];
    const float* wn = (const float*)d_in[2];
    const float* bp = (const float*)d_in[3];
    const float* bn = (const float*)d_in[4];
    float* out = (float*)d_out;

    const int smem_bytes = MT * RA + KCHUNK * RB;   // 70656
    cudaFuncSetAttribute(memr_gemm_hmma,
                         cudaFuncAttributeMaxDynamicSharedMemorySize, smem_bytes);

    memr_init_kernel<<<128, 256>>>(bp, bn, out);
    dim3 grid(NT, BATCH / MT, KSPLIT);              // 16 x 2 x 4 = 128
    memr_gemm_hmma<<<grid, 256, smem_bytes>>>(x, wp, wn, out);
}